// round 11
// baseline (speedup 1.0000x reference)
#include <cuda_runtime.h>
#include <cstdint>

#define IN_DIM  16
#define OUT_DIM 32
#define BLOCK   256

// Magic-bias quant: byte0 of fma(sat(fma(v,cs1,cs0)), 15, 2^23) is
// round(15*sat(f)) in [0,15] (RNE, identical to FMUL+F2I.RN).
__device__ __forceinline__ unsigned quantb(float v, float cs1, float cs0) {
    float f = __saturatef(fmaf(v, cs1, cs0));            // FFMA.SAT
    return __float_as_uint(fmaf(f, 15.0f, 8388608.0f));  // FFMA (magic 2^23)
}

// Weight planes pre-scaled by 17 so dp4a(nq, w17, 128) = y*17+128 directly
// (max 60*17+128 = 1148; byte1 = round(y/15) exactly for y in [0,60]).
// round is odd on the attainable set (no exact halves), so
// terms = rt(yp) - rt(ym); PRMT packs rt_p in bytes{0,1}, rt_m in bytes{2,3};
// bytes accumulate carry-free; one signed dp4a (sel {+1,+1,-1,-1}, acc
// 0x4B400000) yields float-bits of (12582912 + S) directly (no I2F).

__global__ __launch_bounds__(BLOCK, 4)
void quantlinear_kernel(const float* __restrict__ x,
                        const float* __restrict__ weight,
                        const float* __restrict__ in_max_p,
                        const float* __restrict__ in_min_p,
                        float* __restrict__ out) {
    // per-warp double-buffered q-word slab: 8 warps x 2 bufs x 32 words
    __shared__ __align__(16) unsigned s_q[8][2][32];

    const int t   = threadIdx.x & 31;
    const int wid = threadIdx.x >> 5;
    const int oc2 = t & 15;            // output float2-chunk owned by this lane

    // ---- lane-local prep: build this lane's 2 output rows, no sync --------
    const float in_min = in_min_p[0];
    const float rng    = in_max_p[0] - in_min;
    const float cs1    = 1.0f / rng;
    const float cs0    = -in_min * cs1;

    uint4 WP[2], WM[2];
    float2 BIAS;
    {
        // lane's 32 weights: rows 2*oc2 and 2*oc2+1, 128B contiguous
        const float4* wrow = reinterpret_cast<const float4*>(weight) + oc2 * 8;
        float* bp = reinterpret_cast<float*>(&BIAS);
        #pragma unroll
        for (int jj = 0; jj < 2; jj++) {
            unsigned pw[4], mw[4];
            int S = 0;
            #pragma unroll
            for (int g = 0; g < 4; g++) {
                float4 wf = wrow[jj * 4 + g];
                const float* f = reinterpret_cast<const float*>(&wf);
                unsigned p = 0u, m = 0u;
                #pragma unroll
                for (int kk = 0; kk < 4; kk++) {
                    if (f[kk] > 0.0f) { p |= 17u << (8 * kk); S++; }
                    else if (f[kk] < 0.0f) { m |= 17u << (8 * kk); S--; }
                }
                pw[g] = p; mw[g] = m;
            }
            WP[jj] = make_uint4(pw[0], pw[1], pw[2], pw[3]);
            WM[jj] = make_uint4(mw[0], mw[1], mw[2], mw[3]);
            bp[jj] = in_min * (float)S;
        }
    }

    const int wrow0 = (blockIdx.x * 8 + wid) * 32;
    const float4* __restrict__ xin  = reinterpret_cast<const float4*>(x);
    float2*       __restrict__ out2 = reinterpret_cast<float2*>(out);

    #pragma unroll
    for (int k = 0; k < 4; k++) {
        // lane t holds (row = 8k + t>>2, group = t&3); quantize + byte-pack
        float4 v = xin[(wrow0 + 8 * k) * 4 + t];
        unsigned b0 = quantb(v.x, cs1, cs0);
        unsigned b1 = quantb(v.y, cs1, cs0);
        unsigned b2 = quantb(v.z, cs1, cs0);
        unsigned b3 = quantb(v.w, cs1, cs0);
        unsigned q  = __byte_perm(__byte_perm(b0, b1, 0x0040),
                                  __byte_perm(b2, b3, 0x0040), 0x5410);

        // stage warp's 32 q-words; double buffer removes WAR sync
        s_q[wid][k & 1][t] = q;
        __syncwarp();

        #pragma unroll
        for (int h = 0; h < 4; h++) {
            // lane t computes local row r = 2h + (t>>4); one LDS.128 fetches
            // its 4 group words (16 lanes broadcast same 16B line)
            int r = 2 * h + (t >> 4);
            uint4 NQ = *reinterpret_cast<const uint4*>(&s_q[wid][k & 1][r * 4]);

            float2 res;
            float* rp = reinterpret_cast<float*>(&res);
            const float* bp = reinterpret_cast<const float*>(&BIAS);
            #pragma unroll
            for (int jj = 0; jj < 2; jj++) {
                const unsigned* wp = reinterpret_cast<const unsigned*>(&WP[jj]);
                const unsigned* wm = reinterpret_cast<const unsigned*>(&WM[jj]);

                // u = y*17 + 128; rt = byte1(u)
                unsigned up0 = __dp4a(NQ.x, wp[0], 128u), um0 = __dp4a(NQ.x, wm[0], 128u);
                unsigned up1 = __dp4a(NQ.y, wp[1], 128u), um1 = __dp4a(NQ.y, wm[1], 128u);
                unsigned up2 = __dp4a(NQ.z, wp[2], 128u), um2 = __dp4a(NQ.z, wm[2], 128u);
                unsigned up3 = __dp4a(NQ.w, wp[3], 128u), um3 = __dp4a(NQ.w, wm[3], 128u);

                // {rt_p, 0, rt_m, 0} and {0, rt_p, 0, rt_m}
                unsigned p0 = __byte_perm(up0, um0, 0x7531);
                unsigned p1 = __byte_perm(up1, um1, 0x5713);
                unsigned p2 = __byte_perm(up2, um2, 0x7531);
                unsigned p3 = __byte_perm(up3, um3, 0x5713);

                unsigned V = (p0 + p1) + (p2 + p3);   // byte lanes, max 16 each
                // signed dp4a: +p bytes, -m bytes, acc = float magic 2^23+2^22
                int Sb = __dp4a((int)V, (int)0xFFFF0101u, (int)0x4B400000);
                float Sf = __int_as_float(Sb) - 12582912.0f;   // exact S
                rp[jj] = fmaf(Sf, rng, bp[jj]);
            }
            // warp = 2 rows x 128B contiguous -> coalesced STG.64
            out2[(wrow0 + 8 * k + r) * 16 + oc2] = res;
        }
    }
}

extern "C" void kernel_launch(void* const* d_in, const int* in_sizes, int n_in,
                              void* d_out, int out_size) {
    const float* x      = (const float*)d_in[0];
    const float* weight = (const float*)d_in[1];
    // d_in[2] = scale (unused in forward)
    const float* in_max = (const float*)d_in[3];
    const float* in_min = (const float*)d_in[4];
    float* out = (float*)d_out;

    int B = in_sizes[0] / IN_DIM;   // 2,097,152

    int blocks = B / BLOCK;         // 256 rows per block (8 warps x 32 rows)
    quantlinear_kernel<<<blocks, BLOCK>>>(x, weight, in_max, in_min, out);
}

// round 12
// speedup vs baseline: 1.4247x; 1.4247x over previous
#include <cuda_runtime.h>
#include <cstdint>

#define IN_DIM  16
#define OUT_DIM 32
#define BLOCK   256

// Magic-bias quant: byte0 of fma(sat(fma(v,cs1,cs0)), 15, 2^23) is
// round(15*sat(f)) in [0,15] (RNE, identical to FMUL+F2I.RN).
__device__ __forceinline__ unsigned quantb(float v, float cs1, float cs0) {
    float f = __saturatef(fmaf(v, cs1, cs0));            // FFMA.SAT
    return __float_as_uint(fmaf(f, 15.0f, 8388608.0f));  // FFMA (magic 2^23)
}

// Weight planes pre-scaled by 17 so dp4a(nq, w17, 128) = y*17+128 directly
// (max 60*17+128 = 1148; byte1 = round(y/15) exactly for y in [0,60]).
// round is odd on the attainable set (no exact halves), so
// terms = rt(yp) - rt(ym); PRMT packs rt_p in bytes{0,1}, rt_m in bytes{2,3};
// bytes accumulate carry-free; one signed dp4a (sel {+1,+1,-1,-1}, acc
// 0x4B400000) yields float-bits of (12582912 + S) directly (no I2F).

__global__ __launch_bounds__(BLOCK, 4)
void quantlinear_kernel(const float* __restrict__ x,
                        const float* __restrict__ weight,
                        const float* __restrict__ in_max_p,
                        const float* __restrict__ in_min_p,
                        float* __restrict__ out) {
    __shared__ __align__(16) uint4 s_wp17[OUT_DIM];
    __shared__ __align__(16) uint4 s_wm17[OUT_DIM];
    __shared__ __align__(16) float s_bias[OUT_DIM];
    // per-warp double-buffered q-word slab: 8 warps x 2 bufs x 32 words
    __shared__ __align__(16) unsigned s_q[8][2][32];

    const int t   = threadIdx.x & 31;
    const int wid = threadIdx.x >> 5;
    const int oc2 = t & 15;            // output float2-chunk owned by this lane

    const int wrow0 = (blockIdx.x * 8 + wid) * 32;
    const float4* __restrict__ xin  = reinterpret_cast<const float4*>(x);
    float2*       __restrict__ out2 = reinterpret_cast<float2*>(out);

    // ---- issue k=0 input load FIRST so it overlaps the weight-table build --
    float4 v0 = xin[wrow0 * 4 + t];

    const float in_min = in_min_p[0];
    const float rng    = in_max_p[0] - in_min;
    const float cs1    = 1.0f / rng;
    const float cs0    = -in_min * cs1;

    // ---- fused prep: warp 0 builds w17/bias tables (one output per lane) --
    if (threadIdx.x < OUT_DIM) {
        int o = threadIdx.x;
        unsigned p[4] = {0u, 0u, 0u, 0u};
        unsigned m[4] = {0u, 0u, 0u, 0u};
        int S = 0;
        #pragma unroll
        for (int i = 0; i < IN_DIM; i++) {
            float wf = weight[o * IN_DIM + i];
            int s = (wf > 0.0f) - (wf < 0.0f);
            S += s;
            int g = i >> 2, k = i & 3;
            if (s > 0) p[g] |= 17u << (8 * k);
            if (s < 0) m[g] |= 17u << (8 * k);
        }
        s_wp17[o] = make_uint4(p[0], p[1], p[2], p[3]);
        s_wm17[o] = make_uint4(m[0], m[1], m[2], m[3]);
        s_bias[o] = in_min * (float)S;
    }
    __syncthreads();

    // ---- per-lane persistent weights + bias --------------------------------
    uint4 WP[2], WM[2];
    #pragma unroll
    for (int jj = 0; jj < 2; jj++) {
        WP[jj] = s_wp17[oc2 * 2 + jj];
        WM[jj] = s_wm17[oc2 * 2 + jj];
    }
    const float2 BIAS = reinterpret_cast<const float2*>(s_bias)[oc2];

    #pragma unroll
    for (int k = 0; k < 4; k++) {
        // lane t holds (row = 8k + t>>2, group = t&3); quantize + byte-pack
        float4 v = (k == 0) ? v0 : xin[(wrow0 + 8 * k) * 4 + t];
        unsigned b0 = quantb(v.x, cs1, cs0);
        unsigned b1 = quantb(v.y, cs1, cs0);
        unsigned b2 = quantb(v.z, cs1, cs0);
        unsigned b3 = quantb(v.w, cs1, cs0);
        unsigned q  = __byte_perm(__byte_perm(b0, b1, 0x0040),
                                  __byte_perm(b2, b3, 0x0040), 0x5410);

        // stage warp's 32 q-words; double buffer removes WAR sync
        s_q[wid][k & 1][t] = q;
        __syncwarp();

        #pragma unroll
        for (int h = 0; h < 4; h++) {
            // lane t computes local row r = 2h + (t>>4); one LDS.128 fetches
            // its 4 group words (16 lanes broadcast same 16B line)
            int r = 2 * h + (t >> 4);
            uint4 NQ = *reinterpret_cast<const uint4*>(&s_q[wid][k & 1][r * 4]);

            float2 res;
            float* rp = reinterpret_cast<float*>(&res);
            const float* bp = reinterpret_cast<const float*>(&BIAS);
            #pragma unroll
            for (int jj = 0; jj < 2; jj++) {
                const unsigned* wp = reinterpret_cast<const unsigned*>(&WP[jj]);
                const unsigned* wm = reinterpret_cast<const unsigned*>(&WM[jj]);

                // u = y*17 + 128; rt = byte1(u)
                unsigned up0 = __dp4a(NQ.x, wp[0], 128u), um0 = __dp4a(NQ.x, wm[0], 128u);
                unsigned up1 = __dp4a(NQ.y, wp[1], 128u), um1 = __dp4a(NQ.y, wm[1], 128u);
                unsigned up2 = __dp4a(NQ.z, wp[2], 128u), um2 = __dp4a(NQ.z, wm[2], 128u);
                unsigned up3 = __dp4a(NQ.w, wp[3], 128u), um3 = __dp4a(NQ.w, wm[3], 128u);

                // {rt_p, 0, rt_m, 0} and {0, rt_p, 0, rt_m}
                unsigned p0 = __byte_perm(up0, um0, 0x7531);
                unsigned p1 = __byte_perm(up1, um1, 0x5713);
                unsigned p2 = __byte_perm(up2, um2, 0x7531);
                unsigned p3 = __byte_perm(up3, um3, 0x5713);

                unsigned V = (p0 + p1) + (p2 + p3);   // byte lanes, max 16 each
                // signed dp4a: +p bytes, -m bytes, acc = float magic 2^23+2^22
                int Sb = __dp4a((int)V, (int)0xFFFF0101u, (int)0x4B400000);
                float Sf = __int_as_float(Sb) - 12582912.0f;   // exact S
                rp[jj] = fmaf(Sf, rng, bp[jj]);
            }
            // warp = 2 rows x 128B contiguous -> coalesced STG.64
            out2[(wrow0 + 8 * k + r) * 16 + oc2] = res;
        }
    }
}

extern "C" void kernel_launch(void* const* d_in, const int* in_sizes, int n_in,
                              void* d_out, int out_size) {
    const float* x      = (const float*)d_in[0];
    const float* weight = (const float*)d_in[1];
    // d_in[2] = scale (unused in forward)
    const float* in_max = (const float*)d_in[3];
    const float* in_min = (const float*)d_in[4];
    float* out = (float*)d_out;

    int B = in_sizes[0] / IN_DIM;   // 2,097,152

    int blocks = B / BLOCK;         // 256 rows per block (8 warps x 32 rows)
    quantlinear_kernel<<<blocks, BLOCK>>>(x, weight, in_max, in_min, out);
}

// round 13
// speedup vs baseline: 1.4928x; 1.0478x over previous
#include <cuda_runtime.h>
#include <cstdint>

#define IN_DIM  16
#define OUT_DIM 32
#define BLOCK   256

// Launch-invariant precomputed state (written by prep kernel each launch).
// Weight planes pre-scaled by 17 so dp4a(nq, w17, 128) = y*17+128 directly
// (max 60*17+128 = 1148; byte1 = round(y/15) exactly for y in [0,60]).
__device__ uint4  g_wp17[OUT_DIM];  // plus-plane  bytes {0,17}
__device__ uint4  g_wm17[OUT_DIM];  // minus-plane bytes {0,17}
__device__ float  g_bias[OUT_DIM];  // in_min * sum_i sign(w[o,i])
__device__ float  g_cs1;            // 1 / rng
__device__ float  g_cs0;            // -in_min / rng
__device__ float  g_rng;            // in_max - in_min

__global__ void prep_kernel(const float* __restrict__ weight,
                            const float* __restrict__ in_max_p,
                            const float* __restrict__ in_min_p) {
    int o = threadIdx.x;
    float in_min = in_min_p[0];
    float rng = in_max_p[0] - in_min;
    if (o == 0) {
        g_rng = rng;
        g_cs1 = 1.0f / rng;
        g_cs0 = -in_min / rng;
    }
    if (o < OUT_DIM) {
        unsigned p[4] = {0u, 0u, 0u, 0u};
        unsigned m[4] = {0u, 0u, 0u, 0u};
        int S = 0;
        #pragma unroll
        for (int i = 0; i < IN_DIM; i++) {
            float wf = weight[o * IN_DIM + i];
            int s = (wf > 0.0f) - (wf < 0.0f);
            S += s;
            int g = i >> 2, k = i & 3;
            if (s > 0) p[g] |= 17u << (8 * k);
            if (s < 0) m[g] |= 17u << (8 * k);
        }
        g_wp17[o] = make_uint4(p[0], p[1], p[2], p[3]);
        g_wm17[o] = make_uint4(m[0], m[1], m[2], m[3]);
        g_bias[o] = in_min * (float)S;
    }
    // make table writes visible, then release PDL-dependent grid
    __threadfence();
    asm volatile("griddepcontrol.launch_dependents;");
}

// Magic-bias quant: byte0 of fma(sat(fma(v,cs1,cs0)), 15, 2^23) is
// round(15*sat(f)) in [0,15] (RNE, identical to FMUL+F2I.RN).
__device__ __forceinline__ unsigned quantb(float v, float cs1, float cs0) {
    float f = __saturatef(fmaf(v, cs1, cs0));            // FFMA.SAT
    return __float_as_uint(fmaf(f, 15.0f, 8388608.0f));  // FFMA (magic 2^23)
}

// round is odd on the attainable set (no exact halves), so
// terms = rt(yp) - rt(ym); PRMT packs rt_p in bytes{0,1}, rt_m in bytes{2,3};
// bytes accumulate carry-free; one signed dp4a (sel {+1,+1,-1,-1}, acc
// 0x4B400000) yields float-bits of (12582912 + S) directly (no I2F).

__global__ __launch_bounds__(BLOCK, 4)
void quantlinear_kernel(const float* __restrict__ x,
                        float* __restrict__ out) {
    // PDL: wait for prep's tables before reading them
    asm volatile("griddepcontrol.wait;" ::: "memory");

    // per-warp double-buffered q-word slab: 8 warps x 2 bufs x 32 words
    __shared__ __align__(16) unsigned s_q[8][2][32];

    const int t   = threadIdx.x & 31;
    const int wid = threadIdx.x >> 5;
    const int oc2 = t & 15;            // output float2-chunk owned by this lane

    // ---- per-lane persistent weights + bias (coalesced one-time loads) ----
    uint4 WP[2], WM[2];
    #pragma unroll
    for (int jj = 0; jj < 2; jj++) {
        WP[jj] = g_wp17[oc2 * 2 + jj];
        WM[jj] = g_wm17[oc2 * 2 + jj];
    }
    const float2 BIAS = reinterpret_cast<const float2*>(g_bias)[oc2];
    const float cs1 = g_cs1;
    const float cs0 = g_cs0;
    const float rng = g_rng;

    const int wrow0 = (blockIdx.x * 8 + wid) * 32;
    const float4* __restrict__ xin  = reinterpret_cast<const float4*>(x);
    float2*       __restrict__ out2 = reinterpret_cast<float2*>(out);

    #pragma unroll
    for (int k = 0; k < 4; k++) {
        // lane t holds (row = 8k + t>>2, group = t&3); quantize + byte-pack
        float4 v = xin[(wrow0 + 8 * k) * 4 + t];
        unsigned b0 = quantb(v.x, cs1, cs0);
        unsigned b1 = quantb(v.y, cs1, cs0);
        unsigned b2 = quantb(v.z, cs1, cs0);
        unsigned b3 = quantb(v.w, cs1, cs0);
        unsigned q  = __byte_perm(__byte_perm(b0, b1, 0x0040),
                                  __byte_perm(b2, b3, 0x0040), 0x5410);

        // stage warp's 32 q-words; double buffer removes WAR sync
        s_q[wid][k & 1][t] = q;
        __syncwarp();

        #pragma unroll
        for (int h = 0; h < 4; h++) {
            // lane t computes local row r = 2h + (t>>4); one LDS.128 fetches
            // its 4 group words (16 lanes broadcast same 16B line)
            int r = 2 * h + (t >> 4);
            uint4 NQ = *reinterpret_cast<const uint4*>(&s_q[wid][k & 1][r * 4]);

            float2 res;
            float* rp = reinterpret_cast<float*>(&res);
            const float* bp = reinterpret_cast<const float*>(&BIAS);
            #pragma unroll
            for (int jj = 0; jj < 2; jj++) {
                const unsigned* wp = reinterpret_cast<const unsigned*>(&WP[jj]);
                const unsigned* wm = reinterpret_cast<const unsigned*>(&WM[jj]);

                // u = y*17 + 128; rt = byte1(u)
                unsigned up0 = __dp4a(NQ.x, wp[0], 128u), um0 = __dp4a(NQ.x, wm[0], 128u);
                unsigned up1 = __dp4a(NQ.y, wp[1], 128u), um1 = __dp4a(NQ.y, wm[1], 128u);
                unsigned up2 = __dp4a(NQ.z, wp[2], 128u), um2 = __dp4a(NQ.z, wm[2], 128u);
                unsigned up3 = __dp4a(NQ.w, wp[3], 128u), um3 = __dp4a(NQ.w, wm[3], 128u);

                // {rt_p, 0, rt_m, 0} and {0, rt_p, 0, rt_m}
                unsigned p0 = __byte_perm(up0, um0, 0x7531);
                unsigned p1 = __byte_perm(up1, um1, 0x5713);
                unsigned p2 = __byte_perm(up2, um2, 0x7531);
                unsigned p3 = __byte_perm(up3, um3, 0x5713);

                unsigned V = (p0 + p1) + (p2 + p3);   // byte lanes, max 8 each
                // signed dp4a: +p bytes, -m bytes, acc = float magic 2^23+2^22
                int Sb = __dp4a((int)V, (int)0xFFFF0101u, (int)0x4B400000);
                float Sf = __int_as_float(Sb) - 12582912.0f;   // exact S
                rp[jj] = fmaf(Sf, rng, bp[jj]);
            }
            // warp = 2 rows x 128B contiguous -> coalesced STG.64
            out2[(wrow0 + 8 * k + r) * 16 + oc2] = res;
        }
    }
}

extern "C" void kernel_launch(void* const* d_in, const int* in_sizes, int n_in,
                              void* d_out, int out_size) {
    const float* x      = (const float*)d_in[0];
    const float* weight = (const float*)d_in[1];
    // d_in[2] = scale (unused in forward)
    const float* in_max = (const float*)d_in[3];
    const float* in_min = (const float*)d_in[4];
    float* out = (float*)d_out;

    int B = in_sizes[0] / IN_DIM;   // 2,097,152

    prep_kernel<<<1, 32>>>(weight, in_max, in_min);

    // Main kernel with PDL: its launch/scheduling overlaps prep execution.
    int blocks = B / BLOCK;         // 256 rows per block (8 warps x 32 rows)
    cudaLaunchConfig_t cfg = {};
    cfg.gridDim  = dim3((unsigned)blocks);
    cfg.blockDim = dim3(BLOCK);
    cudaLaunchAttribute attr[1];
    attr[0].id = cudaLaunchAttributeProgrammaticStreamSerialization;
    attr[0].val.programmaticStreamSerializationAllowed = 1;
    cfg.attrs = attr;
    cfg.numAttrs = 1;
    cudaLaunchKernelEx(&cfg, quantlinear_kernel, x, out);
}